// round 1
// baseline (speedup 1.0000x reference)
#include <cuda_runtime.h>

// LogicConv3d: B=16, C=3, H=W=32, K=64, P=784, S=64, 7-level soft logic tree.
// d_in: [0]=x f32[16,3,32,32], [1..7]=w0..w6 f32[2^(6-l),64,16],
//       [8]=left_idx i32[64,784,64,3], [9]=right_idx i32[64,784,64,3]
// d_out: f32[16,64,784,1]

#define B_ 16
#define C_ 3
#define H_ 32
#define W_ 32
#define K_ 64
#define P_ 784
#define S_ 64
#define NROWS 127        // 64+32+16+8+4+2+1 tree nodes per k
#define TP 8             // patches per block

// Per-(k,node) gate coefficients: c0 + c1*a + c2*b + c3*a*b
__device__ float4 g_coef[K_ * NROWS];

__constant__ float G4[16][4] = {
    {0,0,0,0},{0,0,0,1},{0,1,0,-1},{0,1,0,0},
    {0,0,1,-1},{0,0,1,0},{0,1,1,-2},{0,1,1,-1},
    {1,-1,-1,1},{1,-1,-1,2},{1,0,-1,0},{1,0,-1,1},
    {1,-1,0,0},{1,-1,0,1},{1,0,0,-1},{1,0,0,0}};

// ---------------------------------------------------------------------------
// Kernel A: softmax(logits) @ GATE_COEFFS  ->  g_coef[k][row] (float4)
// 127*64 = 8128 independent rows; trivially cheap.
// ---------------------------------------------------------------------------
__global__ void coef_kernel(const float* __restrict__ w0, const float* __restrict__ w1,
                            const float* __restrict__ w2, const float* __restrict__ w3,
                            const float* __restrict__ w4, const float* __restrict__ w5,
                            const float* __restrict__ w6) {
    int t = blockIdx.x * blockDim.x + threadIdx.x;
    if (t >= NROWS * K_) return;
    int r = t >> 6;          // tree row 0..126
    int k = t & 63;

    // locate level for this row
    int base = 0, n = 64, l = 0;
    while (r >= base + n) { base += n; n >>= 1; ++l; }
    int s = r - base;

    const float* ws[7] = {w0, w1, w2, w3, w4, w5, w6};
    const float* p = ws[l] + (s * K_ + k) * 16;

    float v[16], m = -1e30f;
#pragma unroll
    for (int i = 0; i < 16; ++i) { v[i] = p[i]; m = fmaxf(m, v[i]); }
    float sum = 0.f, c0 = 0.f, c1 = 0.f, c2 = 0.f, c3 = 0.f;
#pragma unroll
    for (int i = 0; i < 16; ++i) {
        float e = expf(v[i] - m);
        sum += e;
        c0 += e * G4[i][0];
        c1 += e * G4[i][1];
        c2 += e * G4[i][2];
        c3 += e * G4[i][3];
    }
    float inv = 1.f / sum;
    g_coef[k * NROWS + r] = make_float4(c0 * inv, c1 * inv, c2 * inv, c3 * inv);
}

// ---------------------------------------------------------------------------
// Kernel B: main logic-tree evaluation.
// Block = 128 threads = 16 batches x 8 patches, one k per block.
// SMEM: per-block gather offsets (idx read ONCE, shared across all 16 b),
//       per-k coefficients (broadcast), output transpose buffer.
// ---------------------------------------------------------------------------
__global__ __launch_bounds__(128)
void logic_kernel(const float* __restrict__ x,
                  const int* __restrict__ lidx,
                  const int* __restrict__ ridx,
                  float* __restrict__ out) {
    __shared__ int    soff[TP][129];   // [patch][j]; j<64: left s, j>=64: right s. pad->no 2-way conflict
    __shared__ float4 scoef[NROWS];
    __shared__ float  obuf[128];

    const int k   = blockIdx.y;
    const int p0  = blockIdx.x * TP;
    const int tid = threadIdx.x;

    // load this k's 127 gate-coefficient float4s (2KB, contiguous)
    if (tid < NROWS) scoef[tid] = g_coef[k * NROWS + tid];

    // convert (h,w,c) index triples -> flat offsets into one batch slice of x
    for (int e = tid; e < TP * 128; e += 128) {
        int pl = e >> 7;
        int j  = e & 127;
        const int* ip = (j < 64) ? lidx : ridx;
        int s = j & 63;
        int basei = ((k * P_ + p0 + pl) * S_ + s) * 3;
        int h = ip[basei], w = ip[basei + 1], c = ip[basei + 2];
        soff[pl][j] = c * (H_ * W_) + h * W_ + w;
    }
    __syncthreads();

    const int b  = tid & 15;
    const int pl = tid >> 4;
    const float* xb = x + b * (C_ * H_ * W_);

    float cur[64];
    // level 0: gather leaves + gate
#pragma unroll
    for (int s = 0; s < 64; ++s) {
        float fa = xb[soff[pl][s]];
        float fb = xb[soff[pl][64 + s]];
        float4 c = scoef[s];
        // c0 + c1*a + c2*b + c3*a*b  ==  fma(b, fma(c3,a,c2), fma(c1,a,c0))
        cur[s] = fmaf(fb, fmaf(c.w, fa, c.z), fmaf(c.y, fa, c.x));
    }
    // levels 1..6: pairwise tree reduction (fully unrolled, cur stays in regs)
    int cofs = 64;
#pragma unroll
    for (int n = 32; n >= 1; n >>= 1) {
#pragma unroll
        for (int s = 0; s < n; ++s) {
            float fa = cur[2 * s], fb = cur[2 * s + 1];
            float4 c = scoef[cofs + s];
            cur[s] = fmaf(fb, fmaf(c.w, fa, c.z), fmaf(c.y, fa, c.x));
        }
        cofs += n;
    }

    // transpose in SMEM so each 8-lane group stores 32B contiguous
    obuf[b * TP + pl] = cur[0];
    __syncthreads();
    int b2 = tid >> 3, pl2 = tid & 7;
    out[b2 * (K_ * P_) + k * P_ + p0 + pl2] = obuf[tid];
}

// ---------------------------------------------------------------------------
extern "C" void kernel_launch(void* const* d_in, const int* in_sizes, int n_in,
                              void* d_out, int out_size) {
    const float* x  = (const float*)d_in[0];
    const float* w0 = (const float*)d_in[1];
    const float* w1 = (const float*)d_in[2];
    const float* w2 = (const float*)d_in[3];
    const float* w3 = (const float*)d_in[4];
    const float* w4 = (const float*)d_in[5];
    const float* w5 = (const float*)d_in[6];
    const float* w6 = (const float*)d_in[7];
    const int* lidx = (const int*)d_in[8];
    const int* ridx = (const int*)d_in[9];
    float* out = (float*)d_out;

    coef_kernel<<<(NROWS * K_ + 255) / 256, 256>>>(w0, w1, w2, w3, w4, w5, w6);
    logic_kernel<<<dim3(P_ / TP, K_), 128>>>(x, lidx, ridx, out);
}

// round 2
// speedup vs baseline: 2.7989x; 2.7989x over previous
#include <cuda_runtime.h>

// LogicConv3d: B=16, C=3, H=W=32, K=64, P=784, S=64, 7-level soft logic tree.
// d_in: [0]=x f32[16,3,32,32], [1..7]=w0..w6 f32[2^(6-l),64,16],
//       [8]=left_idx i32[64,784,64,3], [9]=right_idx i32[64,784,64,3]
// d_out: f32[16,64,784,1]

#define B_ 16
#define C_ 3
#define HW_ 1024          // 32*32
#define CHW_ 3072
#define K_ 64
#define P_ 784
#define KP_ (K_ * P_)     // 50176
#define NROWS 127
#define TP 16             // patches per block (784 = 49*16)

#define NOFF (KP_ * 128)          // 6,422,528 flat gather offsets
#define OFF_BLOCKS (NOFF / 256)   // 25088 (exact)
#define EXTRA_WORK (NROWS * K_ + CHW_ * B_)   // 8128 + 49152 = 57280

// scratch (static device allocations are the sanctioned path)
__device__ float4 g_coef[K_ * NROWS];     // per-(k,node) gate coeffs
__device__ float  g_xt[CHW_ * B_];        // x transposed: [offset][batch]
__device__ int    g_off[NOFF];            // flat offsets: [k][p][128]

__constant__ float G4[16][4] = {
    {0,0,0,0},{0,0,0,1},{0,1,0,-1},{0,1,0,0},
    {0,0,1,-1},{0,0,1,0},{0,1,1,-2},{0,1,1,-1},
    {1,-1,-1,1},{1,-1,-1,2},{1,0,-1,0},{1,0,-1,1},
    {1,-1,0,0},{1,-1,0,1},{1,0,0,-1},{1,0,0,0}};

// ---------------------------------------------------------------------------
// Fused prep: [blocks < OFF_BLOCKS] idx triples -> flat offsets
//             [rest]                softmax coeffs + x transpose
// ---------------------------------------------------------------------------
__global__ void prep_kernel(const float* __restrict__ x,
                            const float* __restrict__ w0, const float* __restrict__ w1,
                            const float* __restrict__ w2, const float* __restrict__ w3,
                            const float* __restrict__ w4, const float* __restrict__ w5,
                            const float* __restrict__ w6,
                            const int* __restrict__ lidx,
                            const int* __restrict__ ridx) {
    if (blockIdx.x < OFF_BLOCKS) {
        int e  = blockIdx.x * 256 + threadIdx.x;          // < NOFF
        int j  = e & 127;
        int kp = e >> 7;                                   // k*P + p
        const int* ip = (j < 64) ? lidx : ridx;
        int s = j & 63;
        long base = ((long)kp * 64 + s) * 3;
        int h = ip[base], w = ip[base + 1], c = ip[base + 2];
        g_off[e] = c * HW_ + h * 32 + w;
        return;
    }
    int r = (blockIdx.x - OFF_BLOCKS) * 256 + threadIdx.x;
    if (r < NROWS * K_) {
        // softmax(logits) @ GATE_COEFFS
        int row = r >> 6;
        int k   = r & 63;
        int bse = 0, n = 64, l = 0;
        while (row >= bse + n) { bse += n; n >>= 1; ++l; }
        int s = row - bse;
        const float* ws[7] = {w0, w1, w2, w3, w4, w5, w6};
        const float* p = ws[l] + (s * K_ + k) * 16;
        float v[16], m = -1e30f;
#pragma unroll
        for (int i = 0; i < 16; ++i) { v[i] = p[i]; m = fmaxf(m, v[i]); }
        float sum = 0.f, c0 = 0.f, c1 = 0.f, c2 = 0.f, c3 = 0.f;
#pragma unroll
        for (int i = 0; i < 16; ++i) {
            float e = expf(v[i] - m);
            sum += e;
            c0 += e * G4[i][0]; c1 += e * G4[i][1];
            c2 += e * G4[i][2]; c3 += e * G4[i][3];
        }
        float inv = 1.f / sum;
        g_coef[k * NROWS + row] = make_float4(c0 * inv, c1 * inv, c2 * inv, c3 * inv);
        return;
    }
    r -= NROWS * K_;
    if (r < CHW_ * B_) {
        int b = r & 15, off = r >> 4;
        g_xt[r] = x[b * CHW_ + off];
    }
}

// ---------------------------------------------------------------------------
// Main kernel: 64 threads = 4 batch-groups (float4) x 16 patches, one k.
// Depth-first tree eval, 7-deep compile-time stack. Gathers are LDG.128
// from the transposed x (all 16 batch values of an offset are contiguous).
// ---------------------------------------------------------------------------
__device__ __forceinline__ float4 gate4(float4 a, float4 b, float4 c) {
    // c.x + c.y*a + c.z*b + c.w*a*b  ==  fma(b, fma(c3,a,c2), fma(c1,a,c0))
    float4 r;
    r.x = fmaf(b.x, fmaf(c.w, a.x, c.z), fmaf(c.y, a.x, c.x));
    r.y = fmaf(b.y, fmaf(c.w, a.y, c.z), fmaf(c.y, a.y, c.x));
    r.z = fmaf(b.z, fmaf(c.w, a.z, c.z), fmaf(c.y, a.z, c.x));
    r.w = fmaf(b.w, fmaf(c.w, a.w, c.z), fmaf(c.y, a.w, c.x));
    return r;
}

__global__ __launch_bounds__(64)
void logic_kernel(float* __restrict__ out) {
    __shared__ float4 scoef[NROWS];

    const int k   = blockIdx.y;
    const int tid = threadIdx.x;

    for (int i = tid; i < NROWS; i += 64) scoef[i] = g_coef[k * NROWS + i];
    __syncthreads();

    const int bg = tid & 3;            // batch group (4 floats each)
    const int p  = blockIdx.x * TP + (tid >> 2);

    const int*   offp = g_off + ((k * P_ + p) << 7);
    const float* xtb  = g_xt + bg * 4;

    float4 st[7];
    int sp = 0;
#pragma unroll
    for (int s = 0; s < 64; ++s) {
        int oa = offp[s];
        int ob = offp[64 + s];
        float4 A  = *(const float4*)(xtb + oa * 16);
        float4 Bv = *(const float4*)(xtb + ob * 16);
        float4 v = gate4(A, Bv, scoef[s]);
#pragma unroll
        for (int l = 1; l <= 6; ++l) {
            if (((s + 1) & ((1 << l) - 1)) == 0) {
                v = gate4(st[--sp], v, scoef[(128 - (128 >> l)) + (s >> l)]);
            }
        }
        st[sp++] = v;
    }

    float4 r = st[0];
    long ob0 = (long)(bg * 4) * KP_ + k * P_ + p;
    out[ob0]           = r.x;
    out[ob0 + KP_]     = r.y;
    out[ob0 + 2 * KP_] = r.z;
    out[ob0 + 3 * KP_] = r.w;
}

// ---------------------------------------------------------------------------
extern "C" void kernel_launch(void* const* d_in, const int* in_sizes, int n_in,
                              void* d_out, int out_size) {
    const float* x  = (const float*)d_in[0];
    const float* w0 = (const float*)d_in[1];
    const float* w1 = (const float*)d_in[2];
    const float* w2 = (const float*)d_in[3];
    const float* w3 = (const float*)d_in[4];
    const float* w4 = (const float*)d_in[5];
    const float* w5 = (const float*)d_in[6];
    const float* w6 = (const float*)d_in[7];
    const int* lidx = (const int*)d_in[8];
    const int* ridx = (const int*)d_in[9];
    float* out = (float*)d_out;

    int prep_blocks = OFF_BLOCKS + (EXTRA_WORK + 255) / 256;
    prep_kernel<<<prep_blocks, 256>>>(x, w0, w1, w2, w3, w4, w5, w6, lidx, ridx);
    logic_kernel<<<dim3(P_ / TP, K_), 64>>>(out);
}

// round 3
// speedup vs baseline: 5.3018x; 1.8942x over previous
#include <cuda_runtime.h>

// LogicConv3d: B=16, C=3, H=W=32, K=64, P=784, S=64, 7-level soft logic tree.
// d_in: [0]=x f32[16,3,32,32], [1..7]=w0..w6 f32[2^(6-l),64,16],
//       [8]=left_idx i32[64,784,64,3], [9]=right_idx i32[64,784,64,3]
// d_out: f32[16,64,784,1]

#define B_ 16
#define C_ 3
#define HW_ 1024
#define CHW_ 3072
#define K_ 64
#define P_ 784
#define KP_ (K_ * P_)     // 50176
#define NROWS 127
#define TP 16             // patches per block (784 = 49*16)

// scratch
__device__ float4 g_coef[K_ * NROWS];     // per-(k,node) gate coeffs
__device__ float  g_xt[CHW_ * B_];        // x transposed: [offset][batch] (192KB)

__constant__ float G4[16][4] = {
    {0,0,0,0},{0,0,0,1},{0,1,0,-1},{0,1,0,0},
    {0,0,1,-1},{0,0,1,0},{0,1,1,-2},{0,1,1,-1},
    {1,-1,-1,1},{1,-1,-1,2},{1,0,-1,0},{1,0,-1,1},
    {1,-1,0,0},{1,-1,0,1},{1,0,0,-1},{1,0,0,0}};

// ---------------------------------------------------------------------------
// Prep (tiny): softmax coeffs + x transpose. ~57K threads.
// ---------------------------------------------------------------------------
__global__ void prep_kernel(const float* __restrict__ x,
                            const float* __restrict__ w0, const float* __restrict__ w1,
                            const float* __restrict__ w2, const float* __restrict__ w3,
                            const float* __restrict__ w4, const float* __restrict__ w5,
                            const float* __restrict__ w6) {
    int r = blockIdx.x * 256 + threadIdx.x;
    if (r < NROWS * K_) {
        int row = r >> 6;
        int k   = r & 63;
        int bse = 0, n = 64, l = 0;
        while (row >= bse + n) { bse += n; n >>= 1; ++l; }
        int s = row - bse;
        const float* ws[7] = {w0, w1, w2, w3, w4, w5, w6};
        const float* p = ws[l] + (s * K_ + k) * 16;
        float v[16], m = -1e30f;
#pragma unroll
        for (int i = 0; i < 16; ++i) { v[i] = p[i]; m = fmaxf(m, v[i]); }
        float sum = 0.f, c0 = 0.f, c1 = 0.f, c2 = 0.f, c3 = 0.f;
#pragma unroll
        for (int i = 0; i < 16; ++i) {
            float e = expf(v[i] - m);
            sum += e;
            c0 += e * G4[i][0]; c1 += e * G4[i][1];
            c2 += e * G4[i][2]; c3 += e * G4[i][3];
        }
        float inv = 1.f / sum;
        g_coef[k * NROWS + row] = make_float4(c0 * inv, c1 * inv, c2 * inv, c3 * inv);
        return;
    }
    r -= NROWS * K_;
    if (r < CHW_ * B_) {
        int b = r & 15, off = r >> 4;
        g_xt[r] = x[b * CHW_ + off];
    }
}

// ---------------------------------------------------------------------------
// Main kernel: 64 threads = 4 batch-groups (float4) x 16 patches, one k.
// Phase 1: decode this block's idx triples (coalesced global reads) into
//          SMEM flat offsets, interleaved (left,right) per s.
// Phase 2: depth-first tree eval; offsets via conflict-free LDS.64,
//          x gathers via LDG.128 from transposed x (batch-contiguous).
// ---------------------------------------------------------------------------
__device__ __forceinline__ float4 gate4(float4 a, float4 b, float4 c) {
    float4 r;
    r.x = fmaf(b.x, fmaf(c.w, a.x, c.z), fmaf(c.y, a.x, c.x));
    r.y = fmaf(b.y, fmaf(c.w, a.y, c.z), fmaf(c.y, a.y, c.x));
    r.z = fmaf(b.z, fmaf(c.w, a.z, c.z), fmaf(c.y, a.z, c.x));
    r.w = fmaf(b.w, fmaf(c.w, a.w, c.z), fmaf(c.y, a.w, c.x));
    return r;
}

__global__ __launch_bounds__(64)
void logic_kernel(const int* __restrict__ lidx,
                  const int* __restrict__ ridx,
                  float* __restrict__ out) {
    __shared__ int    soff[TP][132];   // [patch][2*s + (0=left,1=right)], pad->bank-free
    __shared__ float4 scoef[NROWS];

    const int k   = blockIdx.y;
    const int p0  = blockIdx.x * TP;
    const int tid = threadIdx.x;

    // coefficients for this k (2KB contiguous, broadcast later)
    for (int i = tid; i < NROWS; i += 64) scoef[i] = g_coef[k * NROWS + i];

    // decode idx triples -> flat offsets. Patches p0..p0+15 are contiguous
    // in lidx/ridx, so these 12B-per-entry reads are fully coalesced.
    {
        const int* lb = lidx + (k * P_ + p0) * (64 * 3);
        const int* rb = ridx + (k * P_ + p0) * (64 * 3);
#pragma unroll
        for (int e = tid; e < TP * 64; e += 64) {
            int pl = e >> 6, s = e & 63;
            int h = lb[3 * e], w = lb[3 * e + 1], c = lb[3 * e + 2];
            soff[pl][2 * s] = c * HW_ + h * 32 + w;
            h = rb[3 * e]; w = rb[3 * e + 1]; c = rb[3 * e + 2];
            soff[pl][2 * s + 1] = c * HW_ + h * 32 + w;
        }
    }
    __syncthreads();

    const int bg = tid & 3;            // batch group (4 floats)
    const int pl = tid >> 2;           // patch lane 0..15
    const float* xtb = g_xt + bg * 4;

    float4 st[7];
    int sp = 0;
#pragma unroll
    for (int s = 0; s < 64; ++s) {
        int2 o = *(const int2*)&soff[pl][2 * s];
        float4 A  = *(const float4*)(xtb + o.x * 16);
        float4 Bv = *(const float4*)(xtb + o.y * 16);
        float4 v = gate4(A, Bv, scoef[s]);
#pragma unroll
        for (int l = 1; l <= 6; ++l) {
            if (((s + 1) & ((1 << l) - 1)) == 0) {
                v = gate4(st[--sp], v, scoef[(128 - (128 >> l)) + (s >> l)]);
            }
        }
        st[sp++] = v;
    }

    float4 r = st[0];
    const int p = p0 + pl;
    long ob0 = (long)(bg * 4) * KP_ + k * P_ + p;
    out[ob0]           = r.x;
    out[ob0 + KP_]     = r.y;
    out[ob0 + 2 * KP_] = r.z;
    out[ob0 + 3 * KP_] = r.w;
}

// ---------------------------------------------------------------------------
extern "C" void kernel_launch(void* const* d_in, const int* in_sizes, int n_in,
                              void* d_out, int out_size) {
    const float* x  = (const float*)d_in[0];
    const float* w0 = (const float*)d_in[1];
    const float* w1 = (const float*)d_in[2];
    const float* w2 = (const float*)d_in[3];
    const float* w3 = (const float*)d_in[4];
    const float* w4 = (const float*)d_in[5];
    const float* w5 = (const float*)d_in[6];
    const float* w6 = (const float*)d_in[7];
    const int* lidx = (const int*)d_in[8];
    const int* ridx = (const int*)d_in[9];
    float* out = (float*)d_out;

    int prep_work = NROWS * K_ + CHW_ * B_;           // 57280
    prep_kernel<<<(prep_work + 255) / 256, 256>>>(x, w0, w1, w2, w3, w4, w5, w6);
    logic_kernel<<<dim3(P_ / TP, K_), 64>>>(lidx, ridx, out);
}